// round 6
// baseline (speedup 1.0000x reference)
#include <cuda_runtime.h>
#include <cuda_bf16.h>

#define BQ 4
#define NQ 2048
#define TILE 128
#define TT (NQ / TILE)                 /* 16 tiles per batch row */
#define PAIRS_B (TT * (TT + 1) / 2)    /* 136 tile pairs (j >= i) */
#define JSPLIT 2                       /* split each j-tile loop across 2 blocks */
#define JLEN (TILE / JSPLIT)           /* 64 inner iterations per block */
#define NBLOCKS (BQ * PAIRS_B * JSPLIT)/* 1088 blocks */

typedef unsigned long long ull;

__device__ float2 g_part[NBLOCKS];        // per-block partials; fully overwritten each launch
__device__ unsigned int g_ticket = 0;     // threadfence-reduction ticket; reset by last block

// ---------- packed f32x2 helpers (sm_103a) ----------
__device__ __forceinline__ ull f2pk(float a, float b) {
    ull r; asm("mov.b64 %0, {%1, %2};" : "=l"(r) : "f"(a), "f"(b)); return r;
}
__device__ __forceinline__ ull bcast(float a) { return f2pk(a, a); }
__device__ __forceinline__ void unpk(ull v, float& a, float& b) {
    asm("mov.b64 {%0, %1}, %2;" : "=f"(a), "=f"(b) : "l"(v));
}
__device__ __forceinline__ ull fma2(ull a, ull b, ull c) {
    ull d; asm("fma.rn.f32x2 %0, %1, %2, %3;" : "=l"(d) : "l"(a), "l"(b), "l"(c)); return d;
}
__device__ __forceinline__ ull add2(ull a, ull b) {
    ull d; asm("add.rn.f32x2 %0, %1, %2;" : "=l"(d) : "l"(a), "l"(b)); return d;
}
__device__ __forceinline__ ull mul2(ull a, ull b) {
    ull d; asm("mul.rn.f32x2 %0, %1, %2;" : "=l"(d) : "l"(a), "l"(b)); return d;
}
// ---------- MUFU approx ----------
__device__ __forceinline__ float rsq_a(float x) { float r; asm("rsqrt.approx.f32 %0, %1;" : "=f"(r) : "f"(x)); return r; }
__device__ __forceinline__ float sqrt_a(float x){ float r; asm("sqrt.approx.f32 %0, %1;"  : "=f"(r) : "f"(x)); return r; }
__device__ __forceinline__ float rcp_a(float x) { float r; asm("rcp.approx.f32 %0, %1;"   : "=f"(r) : "f"(x)); return r; }

// quaternion (w,x,y,z) -> rotation matrix columns c[j]=(R0j,R1j,R2j), no normalization
__device__ __forceinline__ void quat_cols(float qw, float qx, float qy, float qz, float c[9]) {
    c[0] = 1.f - 2.f*(qy*qy + qz*qz);   // R00
    c[1] = 2.f*(qx*qy + qz*qw);         // R10
    c[2] = 2.f*(qx*qz - qy*qw);         // R20
    c[3] = 2.f*(qx*qy - qz*qw);         // R01
    c[4] = 1.f - 2.f*(qx*qx + qz*qz);   // R11
    c[5] = 2.f*(qy*qz + qx*qw);         // R21
    c[6] = 2.f*(qx*qz + qy*qw);         // R02
    c[7] = 2.f*(qy*qz - qx*qw);         // R12
    c[8] = 1.f - 2.f*(qx*qx + qy*qy);   // R22
}

struct OwnP {
    ull x, y, z;          // own position (broadcast)
    ull s2x, s2y, s2z;    // own scale^2
    ull vx, vy, vz;       // own velocity
    ull c[9];             // own rotmat columns
};

// SoA smem field indices for the j-slice (JLEN wide):
// 0..2  : -x, -y, -z          3..5 : sx^2, sy^2, sz^2
// 6..8  : -vx, -vy, -vz       9..17: c0x,c0y,c0z,c1x,c1y,c1z,c2x,c2y,c2z
template<bool DIAG>
__device__ __forceinline__ void inner_loop(const OwnP& o, const float (*sm)[JLEN],
                                           int tid, int mbase,
                                           float& accs, float& accm) {
    const ull E8  = bcast(1e-8f);
    const ull E30 = bcast(1e-30f);
#pragma unroll 2
    for (int mm = 0; mm < JLEN; mm += 2) {
#define LP(f) (*(const ull*)&sm[f][mm])
        ull dx = add2(o.x, LP(0));
        ull dy = add2(o.y, LP(1));
        ull dz = add2(o.z, LP(2));
        ull d2 = fma2(dx, dx, fma2(dy, dy, fma2(dz, dz, E8)));

        // u = d . R_n (own rotation), A2 = sum s2_m,j * u_j^2 + eps
        ull u0 = fma2(dx, o.c[0], fma2(dy, o.c[1], mul2(dz, o.c[2])));
        ull u1 = fma2(dx, o.c[3], fma2(dy, o.c[4], mul2(dz, o.c[5])));
        ull u2 = fma2(dx, o.c[6], fma2(dy, o.c[7], mul2(dz, o.c[8])));
        ull A2 = fma2(LP(3), mul2(u0, u0),
                 fma2(LP(4), mul2(u1, u1),
                 fma2(LP(5), mul2(u2, u2), E30)));

        // v = d . R_m (smem rotation), B2 = sum s2_n,j * v_j^2 + eps
        ull v0 = fma2(dx, LP(9),  fma2(dy, LP(10), mul2(dz, LP(11))));
        ull v1 = fma2(dx, LP(12), fma2(dy, LP(13), mul2(dz, LP(14))));
        ull v2 = fma2(dx, LP(15), fma2(dy, LP(16), mul2(dz, LP(17))));
        ull B2 = fma2(o.s2x, mul2(v0, v0),
                 fma2(o.s2y, mul2(v1, v1),
                 fma2(o.s2z, mul2(v2, v2), E30)));

        // v_rel . d  (unnormalized)
        ull wx = add2(o.vx, LP(6));
        ull wy = add2(o.vy, LP(7));
        ull wz = add2(o.vz, LP(8));
        ull vd = fma2(wx, dx, fma2(wy, dy, mul2(wz, dz)));
#undef LP
        float d2a, d2b, A2a, A2b, B2a, B2b, vda, vdb;
        unpk(d2, d2a, d2b); unpk(A2, A2a, A2b);
        unpk(B2, B2a, B2b); unpk(vd, vda, vdb);

        // scalar tail, half 0 (global point index mbase+mm)
        {
            float rinv = rsq_a(d2a);
            float ovl  = fmaxf(sqrt_a(A2a) + sqrt_a(B2a) - d2a, 0.f);  // overlap/rinv
            float ov   = ovl * rinv;
            float sp   = ov * ov * rcp_a(fmaf(0.1f, ov, 1.f));
            float ms   = (ovl * fmaxf(-vda, 0.f)) * (rinv * rinv);
            if (DIAG) { bool take = (mbase + mm) > tid; sp = take ? sp : 0.f; ms = take ? ms : 0.f; }
            accs += sp; accm += ms;
        }
        // scalar tail, half 1 (global point index mbase+mm+1)
        {
            float rinv = rsq_a(d2b);
            float ovl  = fmaxf(sqrt_a(A2b) + sqrt_a(B2b) - d2b, 0.f);
            float ov   = ovl * rinv;
            float sp   = ov * ov * rcp_a(fmaf(0.1f, ov, 1.f));
            float ms   = (ovl * fmaxf(-vdb, 0.f)) * (rinv * rinv);
            if (DIAG) { bool take = (mbase + mm + 1) > tid; sp = take ? sp : 0.f; ms = take ? ms : 0.f; }
            accs += sp; accm += ms;
        }
    }
}

__global__ __launch_bounds__(TILE) void pair_kernel(const float* __restrict__ xyz,
                                                    const float* __restrict__ scl,
                                                    const float* __restrict__ rot,
                                                    const float* __restrict__ vel,
                                                    float* __restrict__ out) {
    __shared__ __align__(16) float sm[18][JLEN];

    int blk  = blockIdx.x;
    int sub  = blk & (JSPLIT - 1);          // which half of the j tile
    int pb   = blk >> 1;                    // (batch, tile-pair) index
    int b    = pb / PAIRS_B;
    int pidx = pb - b * PAIRS_B;
    int ti = 0, rem = pidx;
    while (rem >= TT - ti) { rem -= TT - ti; ti++; }
    int tj = ti + rem;

    int tid   = threadIdx.x;
    int base  = b * NQ;
    int mbase = sub * JLEN;                 // offset of this block's j-slice within the tile

    // stage j-slice into SoA smem (fused "prep"): threads 0..JLEN-1 each stage one point
    if (tid < JLEN) {
        int g = base + tj * TILE + mbase + tid;
        float4 q = ((const float4*)rot)[g];
        float c[9];
        quat_cols(q.x, q.y, q.z, q.w, c);
        sm[0][tid] = -xyz[3*g+0];  sm[1][tid] = -xyz[3*g+1];  sm[2][tid] = -xyz[3*g+2];
        float s0 = scl[3*g+0], s1 = scl[3*g+1], s2 = scl[3*g+2];
        sm[3][tid] = s0*s0;        sm[4][tid] = s1*s1;        sm[5][tid] = s2*s2;
        sm[6][tid] = -vel[3*g+0];  sm[7][tid] = -vel[3*g+1];  sm[8][tid] = -vel[3*g+2];
#pragma unroll
        for (int k = 0; k < 9; k++) sm[9 + k][tid] = c[k];
    }

    // own point (row n in tile i), packed-broadcast constants
    OwnP o;
    {
        int g = base + ti * TILE + tid;
        float4 q = ((const float4*)rot)[g];
        float c[9];
        quat_cols(q.x, q.y, q.z, q.w, c);
        o.x = bcast(xyz[3*g+0]); o.y = bcast(xyz[3*g+1]); o.z = bcast(xyz[3*g+2]);
        float s0 = scl[3*g+0], s1 = scl[3*g+1], s2 = scl[3*g+2];
        o.s2x = bcast(s0*s0); o.s2y = bcast(s1*s1); o.s2z = bcast(s2*s2);
        o.vx = bcast(vel[3*g+0]); o.vy = bcast(vel[3*g+1]); o.vz = bcast(vel[3*g+2]);
#pragma unroll
        for (int k = 0; k < 9; k++) o.c[k] = bcast(c[k]);
    }
    __syncthreads();

    float accs = 0.f, accm = 0.f;
    if (ti != tj) inner_loop<false>(o, sm, tid, mbase, accs, accm);
    else          inner_loop<true >(o, sm, tid, mbase, accs, accm);

    // block reduce
#pragma unroll
    for (int off = 16; off > 0; off >>= 1) {
        accs += __shfl_down_sync(0xffffffffu, accs, off);
        accm += __shfl_down_sync(0xffffffffu, accm, off);
    }
    __shared__ float red[2][TILE / 32];
    __shared__ bool is_last;
    int wid = tid >> 5, lane = tid & 31;
    if (lane == 0) { red[0][wid] = accs; red[1][wid] = accm; }
    __syncthreads();
    if (tid == 0) {
        float s = 0.f, m = 0.f;
#pragma unroll
        for (int w = 0; w < TILE / 32; w++) { s += red[0][w]; m += red[1][w]; }
        g_part[blk] = make_float2(s, m);
        __threadfence();
        unsigned int t = atomicAdd(&g_ticket, 1u);
        is_last = (t == NBLOCKS - 1);
    }
    __syncthreads();

    // last block folds all partials into the output scalar
    if (is_last) {
        __threadfence();   // acquire: see all g_part writes
        double s = 0.0, m = 0.0;
        for (int i = tid; i < NBLOCKS; i += TILE) {
            float2 p = g_part[i];
            s += (double)p.x;
            m += (double)p.y;
        }
#pragma unroll
        for (int off = 16; off > 0; off >>= 1) {
            s += __shfl_down_sync(0xffffffffu, s, off);
            m += __shfl_down_sync(0xffffffffu, m, off);
        }
        __shared__ double rs[TILE / 32], rm[TILE / 32];
        if (lane == 0) { rs[wid] = s; rm[wid] = m; }
        __syncthreads();
        if (tid == 0) {
            double S = 0.0, M = 0.0;
#pragma unroll
            for (int w = 0; w < TILE / 32; w++) { S += rs[w]; M += rm[w]; }
            const double denom = (double)BQ * (double)NQ * (double)NQ;
            // each unordered pair stands for 2 directed pairs; diagonal contributes 0
            out[0] = (float)((2.0 * S + 0.2 * M) / denom);
            g_ticket = 0;                  // reset for the next (graph-replayed) launch
            __threadfence();
        }
    }
}

extern "C" void kernel_launch(void* const* d_in, const int* in_sizes, int n_in,
                              void* d_out, int out_size) {
    const float* xyz = (const float*)d_in[0];
    const float* scl = (const float*)d_in[1];
    const float* rot = (const float*)d_in[2];
    const float* vel = (const float*)d_in[3];

    pair_kernel<<<NBLOCKS, TILE>>>(xyz, scl, rot, vel, (float*)d_out);
}

// round 9
// speedup vs baseline: 1.0077x; 1.0077x over previous
#include <cuda_runtime.h>
#include <cuda_bf16.h>

#define BQ 4
#define NQ 2048
#define TILE 128
#define TT (NQ / TILE)                 /* 16 tiles per batch row */
#define PAIRS_B (TT * (TT + 1) / 2)    /* 136 tile pairs (j >= i) */
#define NBLOCKS (BQ * PAIRS_B)         /* 544 blocks */

typedef unsigned long long ull;

struct __align__(16) U2 { ull a, b; };    // two packed-f32x2 fields, one LDS.128

__device__ float2 g_part[NBLOCKS];        // per-block partials; fully overwritten each launch
__device__ unsigned int g_ticket = 0;     // threadfence-reduction ticket; reset by last block

// ---------- packed f32x2 helpers (sm_103a) ----------
__device__ __forceinline__ ull f2pk(float a, float b) {
    ull r; asm("mov.b64 %0, {%1, %2};" : "=l"(r) : "f"(a), "f"(b)); return r;
}
__device__ __forceinline__ ull bcast(float a) { return f2pk(a, a); }
__device__ __forceinline__ void unpk(ull v, float& a, float& b) {
    asm("mov.b64 {%0, %1}, %2;" : "=f"(a), "=f"(b) : "l"(v));
}
__device__ __forceinline__ ull fma2(ull a, ull b, ull c) {
    ull d; asm("fma.rn.f32x2 %0, %1, %2, %3;" : "=l"(d) : "l"(a), "l"(b), "l"(c)); return d;
}
__device__ __forceinline__ ull add2(ull a, ull b) {
    ull d; asm("add.rn.f32x2 %0, %1, %2;" : "=l"(d) : "l"(a), "l"(b)); return d;
}
__device__ __forceinline__ ull mul2(ull a, ull b) {
    ull d; asm("mul.rn.f32x2 %0, %1, %2;" : "=l"(d) : "l"(a), "l"(b)); return d;
}
// ---------- MUFU approx ----------
__device__ __forceinline__ float rsq_a(float x) { float r; asm("rsqrt.approx.f32 %0, %1;" : "=f"(r) : "f"(x)); return r; }
__device__ __forceinline__ float sqrt_a(float x){ float r; asm("sqrt.approx.f32 %0, %1;"  : "=f"(r) : "f"(x)); return r; }
__device__ __forceinline__ float rcp_a(float x) { float r; asm("rcp.approx.f32 %0, %1;"   : "=f"(r) : "f"(x)); return r; }

// quaternion (w,x,y,z) -> rotation matrix columns c[j]=(R0j,R1j,R2j), no normalization
__device__ __forceinline__ void quat_cols(float qw, float qx, float qy, float qz, float c[9]) {
    c[0] = 1.f - 2.f*(qy*qy + qz*qz);   // R00
    c[1] = 2.f*(qx*qy + qz*qw);         // R10
    c[2] = 2.f*(qx*qz - qy*qw);         // R20
    c[3] = 2.f*(qx*qy - qz*qw);         // R01
    c[4] = 1.f - 2.f*(qx*qx + qz*qz);   // R11
    c[5] = 2.f*(qy*qz + qx*qw);         // R21
    c[6] = 2.f*(qx*qz + qy*qw);         // R02
    c[7] = 2.f*(qy*qz - qx*qw);         // R12
    c[8] = 1.f - 2.f*(qx*qx + qy*qy);   // R22
}

struct OwnP {
    ull x, y, z;          // own position (broadcast)
    ull s2x, s2y, s2z;    // own scale^2
    ull vx, vy, vz;       // own velocity
    ull c[9];             // own rotmat columns
};

// Paired-field smem layout: record (p, q) holds fields {2p, 2p+1} for j points {2q, 2q+1}.
// field numbering: 0:-x 1:-y 2:-z 3:sx2 4:sy2 5:sz2 6:-vx 7:-vy 8:-vz
//                  9:c0x 10:c0y 11:c0z 12:c1x 13:c1y 14:c1z 15:c2x 16:c2y 17:c2z
template<bool DIAG>
__device__ __forceinline__ void inner_loop(const OwnP& o, const U2 (*sm2)[TILE / 2],
                                           int tid, float& accs, float& accm) {
    const ull E8  = bcast(1e-8f);
    const ull E30 = bcast(1e-30f);
#pragma unroll 4
    for (int mm = 0; mm < TILE; mm += 2) {
        int q = mm >> 1;
        U2 L0 = sm2[0][q];   // {-x, -y}
        U2 L1 = sm2[1][q];   // {-z, sx2}
        U2 L2 = sm2[2][q];   // {sy2, sz2}
        U2 L3 = sm2[3][q];   // {-vx, -vy}
        U2 L4 = sm2[4][q];   // {-vz, c0x}
        U2 L5 = sm2[5][q];   // {c0y, c0z}
        U2 L6 = sm2[6][q];   // {c1x, c1y}
        U2 L7 = sm2[7][q];   // {c1z, c2x}
        U2 L8 = sm2[8][q];   // {c2y, c2z}

        ull dx = add2(o.x, L0.a);
        ull dy = add2(o.y, L0.b);
        ull dz = add2(o.z, L1.a);
        ull d2 = fma2(dx, dx, fma2(dy, dy, fma2(dz, dz, E8)));

        // u = d . R_n (own rotation), A2 = sum s2_m,j * u_j^2 + eps
        ull u0 = fma2(dx, o.c[0], fma2(dy, o.c[1], mul2(dz, o.c[2])));
        ull u1 = fma2(dx, o.c[3], fma2(dy, o.c[4], mul2(dz, o.c[5])));
        ull u2 = fma2(dx, o.c[6], fma2(dy, o.c[7], mul2(dz, o.c[8])));
        ull A2 = fma2(L1.b, mul2(u0, u0),
                 fma2(L2.a, mul2(u1, u1),
                 fma2(L2.b, mul2(u2, u2), E30)));

        // v = d . R_m (smem rotation), B2 = sum s2_n,j * v_j^2 + eps
        ull v0 = fma2(dx, L4.b, fma2(dy, L5.a, mul2(dz, L5.b)));
        ull v1 = fma2(dx, L6.a, fma2(dy, L6.b, mul2(dz, L7.a)));
        ull v2 = fma2(dx, L7.b, fma2(dy, L8.a, mul2(dz, L8.b)));
        ull B2 = fma2(o.s2x, mul2(v0, v0),
                 fma2(o.s2y, mul2(v1, v1),
                 fma2(o.s2z, mul2(v2, v2), E30)));

        // v_rel . d  (unnormalized)
        ull wx = add2(o.vx, L3.a);
        ull wy = add2(o.vy, L3.b);
        ull wz = add2(o.vz, L4.a);
        ull vd = fma2(wx, dx, fma2(wy, dy, mul2(wz, dz)));

        float d2a, d2b, A2a, A2b, B2a, B2b, vda, vdb;
        unpk(d2, d2a, d2b); unpk(A2, A2a, A2b);
        unpk(B2, B2a, B2b); unpk(vd, vda, vdb);

        // scalar tail, half 0 (point mm)
        {
            float rinv = rsq_a(d2a);
            float ovl  = fmaxf(sqrt_a(A2a) + sqrt_a(B2a) - d2a, 0.f);  // overlap/rinv
            float ov   = ovl * rinv;
            float sp   = ov * ov * rcp_a(fmaf(0.1f, ov, 1.f));
            float ms   = (ovl * fmaxf(-vda, 0.f)) * (rinv * rinv);
            if (DIAG) { bool take = mm > tid; sp = take ? sp : 0.f; ms = take ? ms : 0.f; }
            accs += sp; accm += ms;
        }
        // scalar tail, half 1 (point mm+1)
        {
            float rinv = rsq_a(d2b);
            float ovl  = fmaxf(sqrt_a(A2b) + sqrt_a(B2b) - d2b, 0.f);
            float ov   = ovl * rinv;
            float sp   = ov * ov * rcp_a(fmaf(0.1f, ov, 1.f));
            float ms   = (ovl * fmaxf(-vdb, 0.f)) * (rinv * rinv);
            if (DIAG) { bool take = (mm + 1) > tid; sp = take ? sp : 0.f; ms = take ? ms : 0.f; }
            accs += sp; accm += ms;
        }
    }
}

__global__ __launch_bounds__(TILE) void pair_kernel(const float* __restrict__ xyz,
                                                    const float* __restrict__ scl,
                                                    const float* __restrict__ rot,
                                                    const float* __restrict__ vel,
                                                    float* __restrict__ out) {
    __shared__ U2 sm2[9][TILE / 2];

    int blk  = blockIdx.x;
    int b    = blk / PAIRS_B;
    int pidx = blk - b * PAIRS_B;
    int ti = 0, rem = pidx;
    while (rem >= TT - ti) { rem -= TT - ti; ti++; }
    int tj = ti + rem;

    int tid  = threadIdx.x;
    int base = b * NQ;

    // stage tile j into paired-field smem (fused "prep"); scalar scattered stores
    {
        int g = base + tj * TILE + tid;
        float4 qv = ((const float4*)rot)[g];
        float c[9];
        quat_cols(qv.x, qv.y, qv.z, qv.w, c);
        float* sf = (float*)sm2;
        // float index of (field f, point j): ((f>>1)*(TILE/2) + (j>>1))*4 + ((f&1)<<1) + (j&1)
        int jlo = tid & 1, jq = tid >> 1;
#define STF(f, val) sf[(((f) >> 1) * (TILE / 2) + jq) * 4 + (((f) & 1) << 1) + jlo] = (val)
        STF(0, -xyz[3*g+0]);  STF(1, -xyz[3*g+1]);  STF(2, -xyz[3*g+2]);
        float s0 = scl[3*g+0], s1 = scl[3*g+1], s2 = scl[3*g+2];
        STF(3, s0*s0);        STF(4, s1*s1);        STF(5, s2*s2);
        STF(6, -vel[3*g+0]);  STF(7, -vel[3*g+1]);  STF(8, -vel[3*g+2]);
#pragma unroll
        for (int k = 0; k < 9; k++) STF(9 + k, c[k]);
#undef STF
    }

    // own point (row n in tile i), packed-broadcast constants
    OwnP o;
    {
        int g = base + ti * TILE + tid;
        float4 qv = ((const float4*)rot)[g];
        float c[9];
        quat_cols(qv.x, qv.y, qv.z, qv.w, c);
        o.x = bcast(xyz[3*g+0]); o.y = bcast(xyz[3*g+1]); o.z = bcast(xyz[3*g+2]);
        float s0 = scl[3*g+0], s1 = scl[3*g+1], s2 = scl[3*g+2];
        o.s2x = bcast(s0*s0); o.s2y = bcast(s1*s1); o.s2z = bcast(s2*s2);
        o.vx = bcast(vel[3*g+0]); o.vy = bcast(vel[3*g+1]); o.vz = bcast(vel[3*g+2]);
#pragma unroll
        for (int k = 0; k < 9; k++) o.c[k] = bcast(c[k]);
    }
    __syncthreads();

    float accs = 0.f, accm = 0.f;
    if (ti != tj) inner_loop<false>(o, sm2, tid, accs, accm);
    else          inner_loop<true >(o, sm2, tid, accs, accm);

    // block reduce
#pragma unroll
    for (int off = 16; off > 0; off >>= 1) {
        accs += __shfl_down_sync(0xffffffffu, accs, off);
        accm += __shfl_down_sync(0xffffffffu, accm, off);
    }
    __shared__ float red[2][TILE / 32];
    __shared__ bool is_last;
    int wid = tid >> 5, lane = tid & 31;
    if (lane == 0) { red[0][wid] = accs; red[1][wid] = accm; }
    __syncthreads();
    if (tid == 0) {
        float s = 0.f, m = 0.f;
#pragma unroll
        for (int w = 0; w < TILE / 32; w++) { s += red[0][w]; m += red[1][w]; }
        g_part[blk] = make_float2(s, m);
        __threadfence();
        unsigned int t = atomicAdd(&g_ticket, 1u);
        is_last = (t == NBLOCKS - 1);
    }
    __syncthreads();

    // last block folds all partials into the output scalar
    if (is_last) {
        __threadfence();   // acquire: see all g_part writes
        double s = 0.0, m = 0.0;
        for (int i = tid; i < NBLOCKS; i += TILE) {
            float2 p = g_part[i];
            s += (double)p.x;
            m += (double)p.y;
        }
#pragma unroll
        for (int off = 16; off > 0; off >>= 1) {
            s += __shfl_down_sync(0xffffffffu, s, off);
            m += __shfl_down_sync(0xffffffffu, m, off);
        }
        __shared__ double rs[TILE / 32], rm[TILE / 32];
        if (lane == 0) { rs[wid] = s; rm[wid] = m; }
        __syncthreads();
        if (tid == 0) {
            double S = 0.0, M = 0.0;
#pragma unroll
            for (int w = 0; w < TILE / 32; w++) { S += rs[w]; M += rm[w]; }
            const double denom = (double)BQ * (double)NQ * (double)NQ;
            // each unordered pair stands for 2 directed pairs; diagonal contributes 0
            out[0] = (float)((2.0 * S + 0.2 * M) / denom);
            g_ticket = 0;                  // reset for the next (graph-replayed) launch
            __threadfence();
        }
    }
}

extern "C" void kernel_launch(void* const* d_in, const int* in_sizes, int n_in,
                              void* d_out, int out_size) {
    const float* xyz = (const float*)d_in[0];
    const float* scl = (const float*)d_in[1];
    const float* rot = (const float*)d_in[2];
    const float* vel = (const float*)d_in[3];

    pair_kernel<<<NBLOCKS, TILE>>>(xyz, scl, rot, vel, (float*)d_out);
}

// round 11
// speedup vs baseline: 1.0175x; 1.0097x over previous
#include <cuda_runtime.h>
#include <cuda_bf16.h>

#define BQ 4
#define NQ 2048
#define TILE 128
#define TT (NQ / TILE)                 /* 16 tiles per batch row */
#define PAIRS_B (TT * (TT + 1) / 2)    /* 136 tile pairs (j >= i) */
#define NBLOCKS (BQ * PAIRS_B)         /* 544 blocks */
#define NTHREADS 256                   /* 2 j-halves per i-row */
#define JHALF (TILE / 2)               /* 64 inner iterations per thread */

typedef unsigned long long ull;

struct __align__(16) U2 { ull a, b; };    // two packed-f32x2 fields, one LDS.128

__device__ float2 g_part[NBLOCKS];        // per-block partials; fully overwritten each launch
__device__ unsigned int g_ticket = 0;     // threadfence-reduction ticket; reset by last block

// ---------- packed f32x2 helpers (sm_103a) ----------
__device__ __forceinline__ ull f2pk(float a, float b) {
    ull r; asm("mov.b64 %0, {%1, %2};" : "=l"(r) : "f"(a), "f"(b)); return r;
}
__device__ __forceinline__ ull bcast(float a) { return f2pk(a, a); }
__device__ __forceinline__ void unpk(ull v, float& a, float& b) {
    asm("mov.b64 {%0, %1}, %2;" : "=f"(a), "=f"(b) : "l"(v));
}
__device__ __forceinline__ ull fma2(ull a, ull b, ull c) {
    ull d; asm("fma.rn.f32x2 %0, %1, %2, %3;" : "=l"(d) : "l"(a), "l"(b), "l"(c)); return d;
}
__device__ __forceinline__ ull add2(ull a, ull b) {
    ull d; asm("add.rn.f32x2 %0, %1, %2;" : "=l"(d) : "l"(a), "l"(b)); return d;
}
__device__ __forceinline__ ull mul2(ull a, ull b) {
    ull d; asm("mul.rn.f32x2 %0, %1, %2;" : "=l"(d) : "l"(a), "l"(b)); return d;
}
// ---------- MUFU approx ----------
__device__ __forceinline__ float rsq_a(float x) { float r; asm("rsqrt.approx.f32 %0, %1;" : "=f"(r) : "f"(x)); return r; }
__device__ __forceinline__ float sqrt_a(float x){ float r; asm("sqrt.approx.f32 %0, %1;"  : "=f"(r) : "f"(x)); return r; }
__device__ __forceinline__ float rcp_a(float x) { float r; asm("rcp.approx.f32 %0, %1;"   : "=f"(r) : "f"(x)); return r; }

// quaternion (w,x,y,z) -> rotation matrix columns c[j]=(R0j,R1j,R2j), no normalization
__device__ __forceinline__ void quat_cols(float qw, float qx, float qy, float qz, float c[9]) {
    c[0] = 1.f - 2.f*(qy*qy + qz*qz);   // R00
    c[1] = 2.f*(qx*qy + qz*qw);         // R10
    c[2] = 2.f*(qx*qz - qy*qw);         // R20
    c[3] = 2.f*(qx*qy - qz*qw);         // R01
    c[4] = 1.f - 2.f*(qx*qx + qz*qz);   // R11
    c[5] = 2.f*(qy*qz + qx*qw);         // R21
    c[6] = 2.f*(qx*qz + qy*qw);         // R02
    c[7] = 2.f*(qy*qz - qx*qw);         // R12
    c[8] = 1.f - 2.f*(qx*qx + qy*qy);   // R22
}

struct OwnP {
    ull x, y, z;          // own position (broadcast)
    ull s2x, s2y, s2z;    // own scale^2
    ull vx, vy, vz;       // own velocity
    ull c[9];             // own rotmat columns
};

// Paired-field smem layout: record (p, q) holds fields {2p, 2p+1} for j points {2q, 2q+1}.
// field numbering: 0:-x 1:-y 2:-z 3:sx2 4:sy2 5:sz2 6:-vx 7:-vy 8:-vz
//                  9:c0x 10:c0y 11:c0z 12:c1x 13:c1y 14:c1z 15:c2x 16:c2y 17:c2z
template<bool DIAG>
__device__ __forceinline__ void inner_loop(const OwnP& o, const U2 (*sm2)[TILE / 2],
                                           int i, int jbase, float& accs, float& accm) {
    const ull E8  = bcast(1e-8f);
    const ull E30 = bcast(1e-30f);
#pragma unroll 4
    for (int mm = 0; mm < JHALF; mm += 2) {
        int q = (jbase + mm) >> 1;
        U2 L0 = sm2[0][q];   // {-x, -y}
        U2 L1 = sm2[1][q];   // {-z, sx2}
        U2 L2 = sm2[2][q];   // {sy2, sz2}
        U2 L3 = sm2[3][q];   // {-vx, -vy}
        U2 L4 = sm2[4][q];   // {-vz, c0x}
        U2 L5 = sm2[5][q];   // {c0y, c0z}
        U2 L6 = sm2[6][q];   // {c1x, c1y}
        U2 L7 = sm2[7][q];   // {c1z, c2x}
        U2 L8 = sm2[8][q];   // {c2y, c2z}

        ull dx = add2(o.x, L0.a);
        ull dy = add2(o.y, L0.b);
        ull dz = add2(o.z, L1.a);
        ull d2 = fma2(dx, dx, fma2(dy, dy, fma2(dz, dz, E8)));

        // u = d . R_n (own rotation), A2 = sum s2_m,j * u_j^2 + eps
        ull u0 = fma2(dx, o.c[0], fma2(dy, o.c[1], mul2(dz, o.c[2])));
        ull u1 = fma2(dx, o.c[3], fma2(dy, o.c[4], mul2(dz, o.c[5])));
        ull u2 = fma2(dx, o.c[6], fma2(dy, o.c[7], mul2(dz, o.c[8])));
        ull A2 = fma2(L1.b, mul2(u0, u0),
                 fma2(L2.a, mul2(u1, u1),
                 fma2(L2.b, mul2(u2, u2), E30)));

        // v = d . R_m (smem rotation), B2 = sum s2_n,j * v_j^2 + eps
        ull v0 = fma2(dx, L4.b, fma2(dy, L5.a, mul2(dz, L5.b)));
        ull v1 = fma2(dx, L6.a, fma2(dy, L6.b, mul2(dz, L7.a)));
        ull v2 = fma2(dx, L7.b, fma2(dy, L8.a, mul2(dz, L8.b)));
        ull B2 = fma2(o.s2x, mul2(v0, v0),
                 fma2(o.s2y, mul2(v1, v1),
                 fma2(o.s2z, mul2(v2, v2), E30)));

        // v_rel . d  (unnormalized)
        ull wx = add2(o.vx, L3.a);
        ull wy = add2(o.vy, L3.b);
        ull wz = add2(o.vz, L4.a);
        ull vd = fma2(wx, dx, fma2(wy, dy, mul2(wz, dz)));

        float d2a, d2b, A2a, A2b, B2a, B2b, vda, vdb;
        unpk(d2, d2a, d2b); unpk(A2, A2a, A2b);
        unpk(B2, B2a, B2b); unpk(vd, vda, vdb);

        // scalar tail, half 0 (j point jbase+mm)
        {
            float rinv = rsq_a(d2a);
            float ovl  = fmaxf(sqrt_a(A2a) + sqrt_a(B2a) - d2a, 0.f);  // overlap/rinv
            float ov   = ovl * rinv;
            float sp   = ov * ov * rcp_a(fmaf(0.1f, ov, 1.f));
            float ms   = (ovl * fmaxf(-vda, 0.f)) * (rinv * rinv);
            if (DIAG) { bool take = (jbase + mm) > i; sp = take ? sp : 0.f; ms = take ? ms : 0.f; }
            accs += sp; accm += ms;
        }
        // scalar tail, half 1 (j point jbase+mm+1)
        {
            float rinv = rsq_a(d2b);
            float ovl  = fmaxf(sqrt_a(A2b) + sqrt_a(B2b) - d2b, 0.f);
            float ov   = ovl * rinv;
            float sp   = ov * ov * rcp_a(fmaf(0.1f, ov, 1.f));
            float ms   = (ovl * fmaxf(-vdb, 0.f)) * (rinv * rinv);
            if (DIAG) { bool take = (jbase + mm + 1) > i; sp = take ? sp : 0.f; ms = take ? ms : 0.f; }
            accs += sp; accm += ms;
        }
    }
}

__global__ __launch_bounds__(NTHREADS, 3) void pair_kernel(const float* __restrict__ xyz,
                                                           const float* __restrict__ scl,
                                                           const float* __restrict__ rot,
                                                           const float* __restrict__ vel,
                                                           float* __restrict__ out) {
    __shared__ U2 sm2[9][TILE / 2];

    int blk  = blockIdx.x;
    int b    = blk / PAIRS_B;
    int pidx = blk - b * PAIRS_B;
    int ti = 0, rem = pidx;
    while (rem >= TT - ti) { rem -= TT - ti; ti++; }
    int tj = ti + rem;

    int tid   = threadIdx.x;
    int i     = tid & (TILE - 1);       // own row within tile i
    int jbase = (tid >> 7) * JHALF;     // which j-half this thread sweeps
    int base  = b * NQ;

    // stage tile j into paired-field smem (fused "prep"); threads 0..127 stage one point each
    if (tid < TILE) {
        int g = base + tj * TILE + tid;
        float4 qv = ((const float4*)rot)[g];
        float c[9];
        quat_cols(qv.x, qv.y, qv.z, qv.w, c);
        float* sf = (float*)sm2;
        // float index of (field f, point j): ((f>>1)*(TILE/2) + (j>>1))*4 + ((f&1)<<1) + (j&1)
        int jlo = tid & 1, jq = tid >> 1;
#define STF(f, val) sf[(((f) >> 1) * (TILE / 2) + jq) * 4 + (((f) & 1) << 1) + jlo] = (val)
        STF(0, -xyz[3*g+0]);  STF(1, -xyz[3*g+1]);  STF(2, -xyz[3*g+2]);
        float s0 = scl[3*g+0], s1 = scl[3*g+1], s2 = scl[3*g+2];
        STF(3, s0*s0);        STF(4, s1*s1);        STF(5, s2*s2);
        STF(6, -vel[3*g+0]);  STF(7, -vel[3*g+1]);  STF(8, -vel[3*g+2]);
#pragma unroll
        for (int k = 0; k < 9; k++) STF(9 + k, c[k]);
#undef STF
    }

    // own point (row i in tile ti), packed-broadcast constants
    OwnP o;
    {
        int g = base + ti * TILE + i;
        float4 qv = ((const float4*)rot)[g];
        float c[9];
        quat_cols(qv.x, qv.y, qv.z, qv.w, c);
        o.x = bcast(xyz[3*g+0]); o.y = bcast(xyz[3*g+1]); o.z = bcast(xyz[3*g+2]);
        float s0 = scl[3*g+0], s1 = scl[3*g+1], s2 = scl[3*g+2];
        o.s2x = bcast(s0*s0); o.s2y = bcast(s1*s1); o.s2z = bcast(s2*s2);
        o.vx = bcast(vel[3*g+0]); o.vy = bcast(vel[3*g+1]); o.vz = bcast(vel[3*g+2]);
#pragma unroll
        for (int k = 0; k < 9; k++) o.c[k] = bcast(c[k]);
    }
    __syncthreads();

    float accs = 0.f, accm = 0.f;
    if (ti != tj) inner_loop<false>(o, sm2, i, jbase, accs, accm);
    else          inner_loop<true >(o, sm2, i, jbase, accs, accm);

    // block reduce (8 warps)
#pragma unroll
    for (int off = 16; off > 0; off >>= 1) {
        accs += __shfl_down_sync(0xffffffffu, accs, off);
        accm += __shfl_down_sync(0xffffffffu, accm, off);
    }
    __shared__ float red[2][NTHREADS / 32];
    __shared__ bool is_last;
    int wid = tid >> 5, lane = tid & 31;
    if (lane == 0) { red[0][wid] = accs; red[1][wid] = accm; }
    __syncthreads();
    if (tid == 0) {
        float s = 0.f, m = 0.f;
#pragma unroll
        for (int w = 0; w < NTHREADS / 32; w++) { s += red[0][w]; m += red[1][w]; }
        g_part[blk] = make_float2(s, m);
        __threadfence();
        unsigned int t = atomicAdd(&g_ticket, 1u);
        is_last = (t == NBLOCKS - 1);
    }
    __syncthreads();

    // last block folds all partials into the output scalar
    if (is_last) {
        __threadfence();   // acquire: see all g_part writes
        double s = 0.0, m = 0.0;
        for (int idx = tid; idx < NBLOCKS; idx += NTHREADS) {
            float2 p = g_part[idx];
            s += (double)p.x;
            m += (double)p.y;
        }
#pragma unroll
        for (int off = 16; off > 0; off >>= 1) {
            s += __shfl_down_sync(0xffffffffu, s, off);
            m += __shfl_down_sync(0xffffffffu, m, off);
        }
        __shared__ double rs[NTHREADS / 32], rm[NTHREADS / 32];
        if (lane == 0) { rs[wid] = s; rm[wid] = m; }
        __syncthreads();
        if (tid == 0) {
            double S = 0.0, M = 0.0;
#pragma unroll
            for (int w = 0; w < NTHREADS / 32; w++) { S += rs[w]; M += rm[w]; }
            const double denom = (double)BQ * (double)NQ * (double)NQ;
            // each unordered pair stands for 2 directed pairs; diagonal contributes 0
            out[0] = (float)((2.0 * S + 0.2 * M) / denom);
            g_ticket = 0;                  // reset for the next (graph-replayed) launch
            __threadfence();
        }
    }
}

extern "C" void kernel_launch(void* const* d_in, const int* in_sizes, int n_in,
                              void* d_out, int out_size) {
    const float* xyz = (const float*)d_in[0];
    const float* scl = (const float*)d_in[1];
    const float* rot = (const float*)d_in[2];
    const float* vel = (const float*)d_in[3];

    pair_kernel<<<NBLOCKS, NTHREADS>>>(xyz, scl, rot, vel, (float*)d_out);
}